// round 7
// baseline (speedup 1.0000x reference)
#include <cuda_runtime.h>
#include <cstdint>

#define F_FRAMES 64
#define N_PTS    4096
#define M_BOX    128
#define BLOCKS_PER_FRAME 32
#define PTS_PER_BLOCK    (N_PTS / BLOCKS_PER_FRAME)   // 128
#define THREADS  128
#define GRID     (F_FRAMES * BLOCKS_PER_FRAME)        // 2048

// pair-interleaved tables: float4 = (ncx0, ncx1, ncy0, ncy1); 68 pairs = 136 center slots
#define TAB_PAIRS 68

__device__ float    g_sum[F_FRAMES];
__device__ int      g_cnt[F_FRAMES];
__device__ unsigned g_done;

__device__ __forceinline__ uint64_t pack2(float lo, float hi) {
    uint64_t r; asm("mov.b64 %0, {%1, %2};" : "=l"(r) : "f"(lo), "f"(hi)); return r;
}
__device__ __forceinline__ void unpack2(float& lo, float& hi, uint64_t v) {
    asm("mov.b64 {%0, %1}, %2;" : "=f"(lo), "=f"(hi) : "l"(v));
}
__device__ __forceinline__ uint64_t add2(uint64_t a, uint64_t b) {
    uint64_t r; asm("add.rn.f32x2 %0, %1, %2;" : "=l"(r) : "l"(a), "l"(b)); return r;
}
__device__ __forceinline__ uint64_t mul2(uint64_t a, uint64_t b) {
    uint64_t r; asm("mul.rn.f32x2 %0, %1, %2;" : "=l"(r) : "l"(a), "l"(b)); return r;
}
__device__ __forceinline__ uint64_t fma2(uint64_t a, uint64_t b, uint64_t c) {
    uint64_t r; asm("fma.rn.f32x2 %0, %1, %2, %3;" : "=l"(r) : "l"(a), "l"(b), "l"(c)); return r;
}

__global__ __launch_bounds__(THREADS)
void calib_loss_kernel(const float* __restrict__ points,
                       const float* __restrict__ bboxes,
                       const int*   __restrict__ inL,
                       const int*   __restrict__ inR,
                       const float* __restrict__ quat,
                       const float* __restrict__ trans,
                       const float* __restrict__ K,
                       float*       __restrict__ out)
{
    __shared__ float4 sTL[TAB_PAIRS];
    __shared__ float4 sTR[TAB_PAIRS];
    __shared__ int    nCL, nCR;
    __shared__ float  warpSum[THREADS / 32];
    __shared__ int    warpCnt[THREADS / 32];

    const int tid  = threadIdx.x;
    const int lane = tid & 31;
    const int wid  = tid >> 5;
    const int f    = blockIdx.x / BLOCKS_PER_FRAME;
    const int blk  = blockIdx.x % BLOCKS_PER_FRAME;

    if (tid == 0) { nCL = 0; nCR = 0; }
    // sentinel prefill (negated-center convention: -(-1e18) never wins a min)
    for (int i = tid; i < 2 * TAB_PAIRS; i += THREADS) {
        float4 s = make_float4(-1e18f, -1e18f, -1e18f, -1e18f);
        if (i < TAB_PAIRS) sTL[i] = s; else sTR[i - TAB_PAIRS] = s;
    }
    __syncthreads();

    // ---- Compact valid centers (negated) into pair-interleaved tables ----
    {
        int j = tid;                       // M_BOX == THREADS
        const float* bb = bboxes + ((size_t)f * M_BOX + j) * 4;
        float ncx = -bb[0], ncy = -bb[1];
        bool fl = inL[f * M_BOX + j] > 0;
        bool fr = inR[f * M_BOX + j] > 0;
        unsigned ml = __ballot_sync(0xffffffffu, fl);
        if (ml) {
            int leader = __ffs(ml) - 1;
            int base = 0;
            if (lane == leader) base = atomicAdd(&nCL, __popc(ml));
            base = __shfl_sync(0xffffffffu, base, leader);
            if (fl) {
                int i = base + __popc(ml & ((1u << lane) - 1u));
                float* e = (float*)&sTL[i >> 1];
                e[i & 1] = ncx; e[2 + (i & 1)] = ncy;
            }
        }
        unsigned mr = __ballot_sync(0xffffffffu, fr);
        if (mr) {
            int leader = __ffs(mr) - 1;
            int base = 0;
            if (lane == leader) base = atomicAdd(&nCR, __popc(mr));
            base = __shfl_sync(0xffffffffu, base, leader);
            if (fr) {
                int i = base + __popc(mr & ((1u << lane) - 1u));
                float* e = (float*)&sTR[i >> 1];
                e[i & 1] = ncx; e[2 + (i & 1)] = ncy;
            }
        }
    }

    // ---- Fold projection: A = K@R (normalized quaternion), b = K@t ----
    const float oqx = quat[0], oqy = quat[1], oqz = quat[2], oqw = quat[3];
    float qn = rsqrtf(oqx*oqx + oqy*oqy + oqz*oqz + oqw*oqw);
    float qx = oqx*qn, qy = oqy*qn, qz = oqz*qn, qw = oqw*qn;
    float R00 = 1.f - 2.f*(qy*qy + qz*qz), R01 = 2.f*(qx*qy - qz*qw), R02 = 2.f*(qx*qz + qy*qw);
    float R10 = 2.f*(qx*qy + qz*qw), R11 = 1.f - 2.f*(qx*qx + qz*qz), R12 = 2.f*(qy*qz - qx*qw);
    float R20 = 2.f*(qx*qz - qy*qw), R21 = 2.f*(qy*qz + qx*qw), R22 = 1.f - 2.f*(qx*qx + qy*qy);
    const float tx = trans[0], ty = trans[1], tz = trans[2];
    const float k00 = K[0], k01 = K[1], k02 = K[2];
    const float k10 = K[3], k11 = K[4], k12 = K[5];
    const float k20 = K[6], k21 = K[7], k22 = K[8];
    float a00 = k00*R00 + k01*R10 + k02*R20, a01 = k00*R01 + k01*R11 + k02*R21, a02 = k00*R02 + k01*R12 + k02*R22;
    float a10 = k10*R00 + k11*R10 + k12*R20, a11 = k10*R01 + k11*R11 + k12*R21, a12 = k10*R02 + k11*R12 + k12*R22;
    float a20 = k20*R00 + k21*R10 + k22*R20, a21 = k20*R01 + k21*R11 + k22*R21, a22 = k20*R02 + k21*R12 + k22*R22;
    float b0 = k00*tx + k01*ty + k02*tz;
    float b1 = k10*tx + k11*ty + k12*tz;
    float b2 = k20*tx + k21*ty + k22*tz;

    __syncthreads();

    const int cntL = nCL, cntR = nCR;
    // ONE blockwide loop bound for both tables: multiple of 8 centers (4 pairs)
    const int maxC   = (cntL > cntR) ? cntL : cntR;
    const int nPairs = ((maxC + 7) & ~7) >> 1;

    // ---- One point per thread: packed-f32x2 scan, unroll 4, uniform trip count ----
    float accS = 0.f;
    int   accC = 0;
    {
        int n = blk * PTS_PER_BLOCK + tid;
        const float* pt = points + ((size_t)f * N_PTS + n) * 5;
        float x  = pt[0], y = pt[1], z = pt[2], vy = pt[4];

        const ulonglong2* cp = (vy > 0.f) ? (const ulonglong2*)sTL
                                          : (const ulonglong2*)sTR;
        const bool pv = ((vy > 0.f) && (cntL > 0)) || ((vy < 0.f) && (cntR > 0));

        float w  = fmaf(a20, x, fmaf(a21, y, fmaf(a22, z, b2)));
        float iw = __fdividef(1.f, w);
        float u  = fmaf(a00, x, fmaf(a01, y, fmaf(a02, z, b0))) * iw;
        float v  = fmaf(a10, x, fmaf(a11, y, fmaf(a12, z, b1))) * iw;
        uint64_t UU = pack2(u, u);
        uint64_t VV = pack2(v, v);

        float m0 = 3.9e37f, m1 = 3.9e37f, m2 = 3.9e37f, m3 = 3.9e37f;
        float m4 = 3.9e37f, m5 = 3.9e37f, m6 = 3.9e37f, m7 = 3.9e37f;
        for (int k = 0; k < nPairs; k += 4) {
            ulonglong2 t0 = cp[k];
            ulonglong2 t1 = cp[k + 1];
            ulonglong2 t2 = cp[k + 2];
            ulonglong2 t3 = cp[k + 3];
            uint64_t dx0 = add2(UU, t0.x), dy0 = add2(VV, t0.y);
            uint64_t dx1 = add2(UU, t1.x), dy1 = add2(VV, t1.y);
            uint64_t dx2 = add2(UU, t2.x), dy2 = add2(VV, t2.y);
            uint64_t dx3 = add2(UU, t3.x), dy3 = add2(VV, t3.y);
            uint64_t dd0 = fma2(dx0, dx0, mul2(dy0, dy0));
            uint64_t dd1 = fma2(dx1, dx1, mul2(dy1, dy1));
            uint64_t dd2 = fma2(dx2, dx2, mul2(dy2, dy2));
            uint64_t dd3 = fma2(dx3, dx3, mul2(dy3, dy3));
            float a, b, c, d, e, g, h, i;
            unpack2(a, b, dd0);
            unpack2(c, d, dd1);
            unpack2(e, g, dd2);
            unpack2(h, i, dd3);
            m0 = fminf(m0, a); m1 = fminf(m1, b);
            m2 = fminf(m2, c); m3 = fminf(m3, d);
            m4 = fminf(m4, e); m5 = fminf(m5, g);
            m6 = fminf(m6, h); m7 = fminf(m7, i);
        }
        float dmin2 = fminf(fminf(fminf(m0, m1), fminf(m2, m3)),
                            fminf(fminf(m4, m5), fminf(m6, m7)));
        float ds = sqrtf(dmin2);
        float hb = (ds <= 50.f) ? (0.5f * dmin2) : (50.f * (ds - 25.f));
        accS = pv ? hb : 0.f;
        accC = pv ? 1 : 0;
    }

    // ---- Block reduction ----
    #pragma unroll
    for (int o = 16; o > 0; o >>= 1) {
        accS += __shfl_down_sync(0xffffffffu, accS, o);
        accC += __shfl_down_sync(0xffffffffu, accC, o);
    }
    if (lane == 0) { warpSum[wid] = accS; warpCnt[wid] = accC; }
    __syncthreads();

    if (wid == 0) {
        float s = (lane < THREADS / 32) ? warpSum[lane] : 0.f;
        int   c = (lane < THREADS / 32) ? warpCnt[lane] : 0;
        #pragma unroll
        for (int o = 2; o > 0; o >>= 1) {
            s += __shfl_down_sync(0xffffffffu, s, o);
            c += __shfl_down_sync(0xffffffffu, c, o);
        }
        if (lane == 0) {
            if (c > 0) {
                atomicAdd(&g_sum[f], s);
                atomicAdd(&g_cnt[f], c);
            }
            __threadfence();
            unsigned t = atomicAdd(&g_done, 1u);
            if (t == (unsigned)(GRID - 1)) {
                float total = 0.f;
                int   nf = 0;
                #pragma unroll 8
                for (int ff = 0; ff < F_FRAMES; ff++) {
                    float ss = *((volatile float*)&g_sum[ff]);
                    int   cc = *((volatile int*)&g_cnt[ff]);
                    if (cc > 0) { total += ss / (float)cc; nf++; }
                    g_sum[ff] = 0.f;
                    g_cnt[ff] = 0;
                }
                float avg = (nf > 0) ? (total / (float)nf) : 0.f;
                float nrm = sqrtf(oqx*oqx + oqy*oqy + oqz*oqz + oqw*oqw);
                float dq  = 1.f - nrm;
                float reg = 0.01f * (tx*tx + ty*ty + tz*tz + dq*dq);
                out[0] = avg + reg;
                __threadfence();
                g_done = 0u;
            }
        }
    }
}

extern "C" void kernel_launch(void* const* d_in, const int* in_sizes, int n_in,
                              void* d_out, int out_size)
{
    const float* points = (const float*)d_in[0];
    const float* bboxes = (const float*)d_in[1];
    const int*   inL    = (const int*)  d_in[2];
    const int*   inR    = (const int*)  d_in[3];
    const float* quat   = (const float*)d_in[4];
    const float* trans  = (const float*)d_in[5];
    const float* K      = (const float*)d_in[6];
    float*       out    = (float*)d_out;
    (void)in_sizes; (void)n_in; (void)out_size;

    calib_loss_kernel<<<GRID, THREADS>>>(points, bboxes, inL, inR, quat, trans, K, out);
}

// round 8
// speedup vs baseline: 1.0172x; 1.0172x over previous
#include <cuda_runtime.h>
#include <cstdint>

#define F_FRAMES 64
#define N_PTS    4096
#define M_BOX    128
#define BLOCKS_PER_FRAME 16
#define PTS_PER_BLOCK    (N_PTS / BLOCKS_PER_FRAME)   // 256
#define THREADS  256
#define GRID     (F_FRAMES * BLOCKS_PER_FRAME)        // 1024

// pair-interleaved tables: float4 = (ncx0, ncx1, ncy0, ncy1); 68 pairs = 136 center slots
#define TAB_PAIRS 68

__device__ float    g_sum[F_FRAMES];
__device__ int      g_cnt[F_FRAMES];
__device__ unsigned g_done;

__device__ __forceinline__ uint64_t pack2(float lo, float hi) {
    uint64_t r; asm("mov.b64 %0, {%1, %2};" : "=l"(r) : "f"(lo), "f"(hi)); return r;
}
__device__ __forceinline__ void unpack2(float& lo, float& hi, uint64_t v) {
    asm("mov.b64 {%0, %1}, %2;" : "=f"(lo), "=f"(hi) : "l"(v));
}
__device__ __forceinline__ uint64_t add2(uint64_t a, uint64_t b) {
    uint64_t r; asm("add.rn.f32x2 %0, %1, %2;" : "=l"(r) : "l"(a), "l"(b)); return r;
}
__device__ __forceinline__ uint64_t mul2(uint64_t a, uint64_t b) {
    uint64_t r; asm("mul.rn.f32x2 %0, %1, %2;" : "=l"(r) : "l"(a), "l"(b)); return r;
}
__device__ __forceinline__ uint64_t fma2(uint64_t a, uint64_t b, uint64_t c) {
    uint64_t r; asm("fma.rn.f32x2 %0, %1, %2, %3;" : "=l"(r) : "l"(a), "l"(b), "l"(c)); return r;
}

__global__ __launch_bounds__(THREADS)
void calib_loss_kernel(const float* __restrict__ points,
                       const float* __restrict__ bboxes,
                       const int*   __restrict__ inL,
                       const int*   __restrict__ inR,
                       const float* __restrict__ quat,
                       const float* __restrict__ trans,
                       const float* __restrict__ K,
                       float*       __restrict__ out)
{
    __shared__ float4 sTL[TAB_PAIRS];
    __shared__ float4 sTR[TAB_PAIRS];
    __shared__ int    nCL, nCR;
    __shared__ float  warpSum[THREADS / 32];
    __shared__ int    warpCnt[THREADS / 32];

    const int tid  = threadIdx.x;
    const int lane = tid & 31;
    const int wid  = tid >> 5;
    const int f    = blockIdx.x / BLOCKS_PER_FRAME;
    const int blk  = blockIdx.x % BLOCKS_PER_FRAME;

    if (tid == 0) { nCL = 0; nCR = 0; }
    // sentinel prefill (negated-center convention: -(-1e18) never wins a min)
    if (tid < 2 * TAB_PAIRS) {
        float4 s = make_float4(-1e18f, -1e18f, -1e18f, -1e18f);
        if (tid < TAB_PAIRS) sTL[tid] = s; else sTR[tid - TAB_PAIRS] = s;
    }
    __syncthreads();

    // ---- Compact valid centers (negated) into pair-interleaved tables ----
    if (tid < M_BOX) {
        int j = tid;
        const float* bb = bboxes + ((size_t)f * M_BOX + j) * 4;
        float ncx = -bb[0], ncy = -bb[1];
        bool fl = inL[f * M_BOX + j] > 0;
        bool fr = inR[f * M_BOX + j] > 0;
        unsigned ml = __ballot_sync(0xffffffffu, fl);
        if (ml) {
            int leader = __ffs(ml) - 1;
            int base = 0;
            if (lane == leader) base = atomicAdd(&nCL, __popc(ml));
            base = __shfl_sync(0xffffffffu, base, leader);
            if (fl) {
                int i = base + __popc(ml & ((1u << lane) - 1u));
                float* e = (float*)&sTL[i >> 1];
                e[i & 1] = ncx; e[2 + (i & 1)] = ncy;
            }
        }
        unsigned mr = __ballot_sync(0xffffffffu, fr);
        if (mr) {
            int leader = __ffs(mr) - 1;
            int base = 0;
            if (lane == leader) base = atomicAdd(&nCR, __popc(mr));
            base = __shfl_sync(0xffffffffu, base, leader);
            if (fr) {
                int i = base + __popc(mr & ((1u << lane) - 1u));
                float* e = (float*)&sTR[i >> 1];
                e[i & 1] = ncx; e[2 + (i & 1)] = ncy;
            }
        }
    }

    // ---- Fold projection: A = K@R (normalized quaternion), b = K@t ----
    const float oqx = quat[0], oqy = quat[1], oqz = quat[2], oqw = quat[3];
    float qn = rsqrtf(oqx*oqx + oqy*oqy + oqz*oqz + oqw*oqw);
    float qx = oqx*qn, qy = oqy*qn, qz = oqz*qn, qw = oqw*qn;
    float R00 = 1.f - 2.f*(qy*qy + qz*qz), R01 = 2.f*(qx*qy - qz*qw), R02 = 2.f*(qx*qz + qy*qw);
    float R10 = 2.f*(qx*qy + qz*qw), R11 = 1.f - 2.f*(qx*qx + qz*qz), R12 = 2.f*(qy*qz - qx*qw);
    float R20 = 2.f*(qx*qz - qy*qw), R21 = 2.f*(qy*qz + qx*qw), R22 = 1.f - 2.f*(qx*qx + qy*qy);
    const float tx = trans[0], ty = trans[1], tz = trans[2];
    const float k00 = K[0], k01 = K[1], k02 = K[2];
    const float k10 = K[3], k11 = K[4], k12 = K[5];
    const float k20 = K[6], k21 = K[7], k22 = K[8];
    float a00 = k00*R00 + k01*R10 + k02*R20, a01 = k00*R01 + k01*R11 + k02*R21, a02 = k00*R02 + k01*R12 + k02*R22;
    float a10 = k10*R00 + k11*R10 + k12*R20, a11 = k10*R01 + k11*R11 + k12*R21, a12 = k10*R02 + k11*R12 + k12*R22;
    float a20 = k20*R00 + k21*R10 + k22*R20, a21 = k20*R01 + k21*R11 + k22*R21, a22 = k20*R02 + k21*R12 + k22*R22;
    float b0 = k00*tx + k01*ty + k02*tz;
    float b1 = k10*tx + k11*ty + k12*tz;
    float b2 = k20*tx + k21*ty + k22*tz;

    __syncthreads();

    const int cntL = nCL, cntR = nCR;
    // ONE blockwide loop bound for both tables: multiple of 8 centers (4 pairs)
    const int maxC   = (cntL > cntR) ? cntL : cntR;
    const int nPairs = ((maxC + 7) & ~7) >> 1;

    // ---- One point per thread: packed-f32x2 scan, unroll 4, uniform trip count ----
    float accS = 0.f;
    int   accC = 0;
    {
        int n = blk * PTS_PER_BLOCK + tid;
        const float* pt = points + ((size_t)f * N_PTS + n) * 5;
        float x  = pt[0], y = pt[1], z = pt[2], vy = pt[4];

        const ulonglong2* cp = (vy > 0.f) ? (const ulonglong2*)sTL
                                          : (const ulonglong2*)sTR;
        const bool pv = ((vy > 0.f) && (cntL > 0)) || ((vy < 0.f) && (cntR > 0));

        float w  = fmaf(a20, x, fmaf(a21, y, fmaf(a22, z, b2)));
        float iw = __fdividef(1.f, w);
        float u  = fmaf(a00, x, fmaf(a01, y, fmaf(a02, z, b0))) * iw;
        float v  = fmaf(a10, x, fmaf(a11, y, fmaf(a12, z, b1))) * iw;
        uint64_t UU = pack2(u, u);
        uint64_t VV = pack2(v, v);

        float m0 = 3.9e37f, m1 = 3.9e37f, m2 = 3.9e37f, m3 = 3.9e37f;
        float m4 = 3.9e37f, m5 = 3.9e37f, m6 = 3.9e37f, m7 = 3.9e37f;
        for (int k = 0; k < nPairs; k += 4) {
            ulonglong2 t0 = cp[k];
            ulonglong2 t1 = cp[k + 1];
            ulonglong2 t2 = cp[k + 2];
            ulonglong2 t3 = cp[k + 3];
            uint64_t dx0 = add2(UU, t0.x), dy0 = add2(VV, t0.y);
            uint64_t dx1 = add2(UU, t1.x), dy1 = add2(VV, t1.y);
            uint64_t dx2 = add2(UU, t2.x), dy2 = add2(VV, t2.y);
            uint64_t dx3 = add2(UU, t3.x), dy3 = add2(VV, t3.y);
            uint64_t dd0 = fma2(dx0, dx0, mul2(dy0, dy0));
            uint64_t dd1 = fma2(dx1, dx1, mul2(dy1, dy1));
            uint64_t dd2 = fma2(dx2, dx2, mul2(dy2, dy2));
            uint64_t dd3 = fma2(dx3, dx3, mul2(dy3, dy3));
            float a, b, c, d, e, g, h, i;
            unpack2(a, b, dd0);
            unpack2(c, d, dd1);
            unpack2(e, g, dd2);
            unpack2(h, i, dd3);
            m0 = fminf(m0, a); m1 = fminf(m1, b);
            m2 = fminf(m2, c); m3 = fminf(m3, d);
            m4 = fminf(m4, e); m5 = fminf(m5, g);
            m6 = fminf(m6, h); m7 = fminf(m7, i);
        }
        float dmin2 = fminf(fminf(fminf(m0, m1), fminf(m2, m3)),
                            fminf(fminf(m4, m5), fminf(m6, m7)));
        float ds = sqrtf(dmin2);
        float hb = (ds <= 50.f) ? (0.5f * dmin2) : (50.f * (ds - 25.f));
        accS = pv ? hb : 0.f;
        accC = pv ? 1 : 0;
    }

    // ---- Block reduction ----
    #pragma unroll
    for (int o = 16; o > 0; o >>= 1) {
        accS += __shfl_down_sync(0xffffffffu, accS, o);
        accC += __shfl_down_sync(0xffffffffu, accC, o);
    }
    if (lane == 0) { warpSum[wid] = accS; warpCnt[wid] = accC; }
    __syncthreads();

    if (wid == 0) {
        float s = (lane < THREADS / 32) ? warpSum[lane] : 0.f;
        int   c = (lane < THREADS / 32) ? warpCnt[lane] : 0;
        #pragma unroll
        for (int o = 4; o > 0; o >>= 1) {
            s += __shfl_down_sync(0xffffffffu, s, o);
            c += __shfl_down_sync(0xffffffffu, c, o);
        }
        if (lane == 0) {
            if (c > 0) {
                atomicAdd(&g_sum[f], s);
                atomicAdd(&g_cnt[f], c);
            }
            __threadfence();
            unsigned t = atomicAdd(&g_done, 1u);
            if (t == (unsigned)(GRID - 1)) {
                float total = 0.f;
                int   nf = 0;
                #pragma unroll 8
                for (int ff = 0; ff < F_FRAMES; ff++) {
                    float ss = *((volatile float*)&g_sum[ff]);
                    int   cc = *((volatile int*)&g_cnt[ff]);
                    if (cc > 0) { total += ss / (float)cc; nf++; }
                    g_sum[ff] = 0.f;
                    g_cnt[ff] = 0;
                }
                float avg = (nf > 0) ? (total / (float)nf) : 0.f;
                float nrm = sqrtf(oqx*oqx + oqy*oqy + oqz*oqz + oqw*oqw);
                float dq  = 1.f - nrm;
                float reg = 0.01f * (tx*tx + ty*ty + tz*tz + dq*dq);
                out[0] = avg + reg;
                __threadfence();
                g_done = 0u;
            }
        }
    }
}

extern "C" void kernel_launch(void* const* d_in, const int* in_sizes, int n_in,
                              void* d_out, int out_size)
{
    const float* points = (const float*)d_in[0];
    const float* bboxes = (const float*)d_in[1];
    const int*   inL    = (const int*)  d_in[2];
    const int*   inR    = (const int*)  d_in[3];
    const float* quat   = (const float*)d_in[4];
    const float* trans  = (const float*)d_in[5];
    const float* K      = (const float*)d_in[6];
    float*       out    = (float*)d_out;
    (void)in_sizes; (void)n_in; (void)out_size;

    calib_loss_kernel<<<GRID, THREADS>>>(points, bboxes, inL, inR, quat, trans, K, out);
}

// round 9
// speedup vs baseline: 1.0620x; 1.0441x over previous
#include <cuda_runtime.h>
#include <cstdint>

#define F_FRAMES 64
#define N_PTS    4096
#define M_BOX    128
#define BLOCKS_PER_FRAME 16
#define PTS_PER_BLOCK    (N_PTS / BLOCKS_PER_FRAME)   // 256
#define THREADS  256
#define GRID     (F_FRAMES * BLOCKS_PER_FRAME)        // 1024

// pair-interleaved tables: float4 = (ncx0, ncx1, ncy0, ncy1); 66 pairs = 132 center slots
#define TAB_PAIRS 66

__device__ float    g_sum[F_FRAMES];
__device__ int      g_cnt[F_FRAMES];
__device__ unsigned g_done;

__device__ __forceinline__ uint64_t pack2(float lo, float hi) {
    uint64_t r; asm("mov.b64 %0, {%1, %2};" : "=l"(r) : "f"(lo), "f"(hi)); return r;
}
__device__ __forceinline__ void unpack2(float& lo, float& hi, uint64_t v) {
    asm("mov.b64 {%0, %1}, %2;" : "=f"(lo), "=f"(hi) : "l"(v));
}
__device__ __forceinline__ uint64_t add2(uint64_t a, uint64_t b) {
    uint64_t r; asm("add.rn.f32x2 %0, %1, %2;" : "=l"(r) : "l"(a), "l"(b)); return r;
}
__device__ __forceinline__ uint64_t mul2(uint64_t a, uint64_t b) {
    uint64_t r; asm("mul.rn.f32x2 %0, %1, %2;" : "=l"(r) : "l"(a), "l"(b)); return r;
}
__device__ __forceinline__ uint64_t fma2(uint64_t a, uint64_t b, uint64_t c) {
    uint64_t r; asm("fma.rn.f32x2 %0, %1, %2, %3;" : "=l"(r) : "l"(a), "l"(b), "l"(c)); return r;
}

__global__ __launch_bounds__(THREADS)
void calib_loss_kernel(const float* __restrict__ points,
                       const float* __restrict__ bboxes,
                       const int*   __restrict__ inL,
                       const int*   __restrict__ inR,
                       const float* __restrict__ quat,
                       const float* __restrict__ trans,
                       const float* __restrict__ K,
                       float*       __restrict__ out)
{
    __shared__ float4 sTL[TAB_PAIRS];
    __shared__ float4 sTR[TAB_PAIRS];
    __shared__ float  sFold[12];        // a00,a01,a02,a10,a11,a12,a20,a21,a22,b0,b1,b2
    __shared__ int    nCL, nCR;
    __shared__ float  warpSum[THREADS / 32];
    __shared__ int    warpCnt[THREADS / 32];

    const int tid  = threadIdx.x;
    const int lane = tid & 31;
    const int wid  = tid >> 5;
    const int f    = blockIdx.x / BLOCKS_PER_FRAME;
    const int blk  = blockIdx.x % BLOCKS_PER_FRAME;

    if (tid == 0) { nCL = 0; nCR = 0; }
    // sentinel prefill (negated-center convention: -(-1e18) never wins a min)
    if (tid < 2 * TAB_PAIRS) {
        float4 s = make_float4(-1e18f, -1e18f, -1e18f, -1e18f);
        if (tid < TAB_PAIRS) sTL[tid] = s; else sTR[tid - TAB_PAIRS] = s;
    }
    __syncthreads();

    // ---- Compact valid centers (negated) into pair-interleaved tables ----
    if (tid < M_BOX) {
        int j = tid;
        const float* bb = bboxes + ((size_t)f * M_BOX + j) * 4;
        float ncx = -bb[0], ncy = -bb[1];
        bool fl = inL[f * M_BOX + j] > 0;
        bool fr = inR[f * M_BOX + j] > 0;
        unsigned ml = __ballot_sync(0xffffffffu, fl);
        if (ml) {
            int leader = __ffs(ml) - 1;
            int base = 0;
            if (lane == leader) base = atomicAdd(&nCL, __popc(ml));
            base = __shfl_sync(0xffffffffu, base, leader);
            if (fl) {
                int i = base + __popc(ml & ((1u << lane) - 1u));
                float* e = (float*)&sTL[i >> 1];
                e[i & 1] = ncx; e[2 + (i & 1)] = ncy;
            }
        }
        unsigned mr = __ballot_sync(0xffffffffu, fr);
        if (mr) {
            int leader = __ffs(mr) - 1;
            int base = 0;
            if (lane == leader) base = atomicAdd(&nCR, __popc(mr));
            base = __shfl_sync(0xffffffffu, base, leader);
            if (fr) {
                int i = base + __popc(mr & ((1u << lane) - 1u));
                float* e = (float*)&sTR[i >> 1];
                e[i & 1] = ncx; e[2 + (i & 1)] = ncy;
            }
        }
    }

    // ---- Fold projection ONCE per block (thread 0): A = K@R, b = K@t ----
    if (tid == 0) {
        const float oqx = quat[0], oqy = quat[1], oqz = quat[2], oqw = quat[3];
        float qn = rsqrtf(oqx*oqx + oqy*oqy + oqz*oqz + oqw*oqw);
        float qx = oqx*qn, qy = oqy*qn, qz = oqz*qn, qw = oqw*qn;
        float R00 = 1.f - 2.f*(qy*qy + qz*qz), R01 = 2.f*(qx*qy - qz*qw), R02 = 2.f*(qx*qz + qy*qw);
        float R10 = 2.f*(qx*qy + qz*qw), R11 = 1.f - 2.f*(qx*qx + qz*qz), R12 = 2.f*(qy*qz - qx*qw);
        float R20 = 2.f*(qx*qz - qy*qw), R21 = 2.f*(qy*qz + qx*qw), R22 = 1.f - 2.f*(qx*qx + qy*qy);
        const float tx = trans[0], ty = trans[1], tz = trans[2];
        const float k00 = K[0], k01 = K[1], k02 = K[2];
        const float k10 = K[3], k11 = K[4], k12 = K[5];
        const float k20 = K[6], k21 = K[7], k22 = K[8];
        sFold[0]  = k00*R00 + k01*R10 + k02*R20;
        sFold[1]  = k00*R01 + k01*R11 + k02*R21;
        sFold[2]  = k00*R02 + k01*R12 + k02*R22;
        sFold[3]  = k10*R00 + k11*R10 + k12*R20;
        sFold[4]  = k10*R01 + k11*R11 + k12*R21;
        sFold[5]  = k10*R02 + k11*R12 + k12*R22;
        sFold[6]  = k20*R00 + k21*R10 + k22*R20;
        sFold[7]  = k20*R01 + k21*R11 + k22*R21;
        sFold[8]  = k20*R02 + k21*R12 + k22*R22;
        sFold[9]  = k00*tx + k01*ty + k02*tz;
        sFold[10] = k10*tx + k11*ty + k12*tz;
        sFold[11] = k20*tx + k21*ty + k22*tz;
    }
    __syncthreads();

    const float a00 = sFold[0], a01 = sFold[1], a02 = sFold[2];
    const float a10 = sFold[3], a11 = sFold[4], a12 = sFold[5];
    const float a20 = sFold[6], a21 = sFold[7], a22 = sFold[8];
    const float b0  = sFold[9], b1  = sFold[10], b2 = sFold[11];

    const int cntL = nCL, cntR = nCR;
    // ONE blockwide loop bound for both tables: multiple of 4 centers (2 pairs)
    const int maxC   = (cntL > cntR) ? cntL : cntR;
    const int nPairs = ((maxC + 3) & ~3) >> 1;

    // ---- One point per thread: packed-f32x2 scan, uniform trip count ----
    float accS = 0.f;
    int   accC = 0;
    {
        int n = blk * PTS_PER_BLOCK + tid;
        const float* pt = points + ((size_t)f * N_PTS + n) * 5;
        float x  = pt[0], y = pt[1], z = pt[2], vy = pt[4];

        const ulonglong2* cp = (vy > 0.f) ? (const ulonglong2*)sTL
                                          : (const ulonglong2*)sTR;
        const bool pv = ((vy > 0.f) && (cntL > 0)) || ((vy < 0.f) && (cntR > 0));

        float w  = fmaf(a20, x, fmaf(a21, y, fmaf(a22, z, b2)));
        float iw = __fdividef(1.f, w);
        float u  = fmaf(a00, x, fmaf(a01, y, fmaf(a02, z, b0))) * iw;
        float v  = fmaf(a10, x, fmaf(a11, y, fmaf(a12, z, b1))) * iw;
        uint64_t UU = pack2(u, u);
        uint64_t VV = pack2(v, v);

        float m0 = 3.9e37f, m1 = 3.9e37f, m2 = 3.9e37f, m3 = 3.9e37f;
        #pragma unroll 2
        for (int k = 0; k < nPairs; k += 2) {
            ulonglong2 t0 = cp[k];
            ulonglong2 t1 = cp[k + 1];
            uint64_t dx0 = add2(UU, t0.x);       // u - cx (centers stored negated)
            uint64_t dy0 = add2(VV, t0.y);
            uint64_t dx1 = add2(UU, t1.x);
            uint64_t dy1 = add2(VV, t1.y);
            uint64_t dd0 = fma2(dx0, dx0, mul2(dy0, dy0));
            uint64_t dd1 = fma2(dx1, dx1, mul2(dy1, dy1));
            float a, b, c, d;
            unpack2(a, b, dd0);
            unpack2(c, d, dd1);
            m0 = fminf(m0, a); m1 = fminf(m1, b);
            m2 = fminf(m2, c); m3 = fminf(m3, d);
        }
        float dmin2 = fminf(fminf(m0, m1), fminf(m2, m3));
        float ds = sqrtf(dmin2);
        float h  = (ds <= 50.f) ? (0.5f * dmin2) : (50.f * (ds - 25.f));
        accS = pv ? h : 0.f;
        accC = pv ? 1 : 0;
    }

    // ---- Block reduction ----
    #pragma unroll
    for (int o = 16; o > 0; o >>= 1) {
        accS += __shfl_down_sync(0xffffffffu, accS, o);
        accC += __shfl_down_sync(0xffffffffu, accC, o);
    }
    if (lane == 0) { warpSum[wid] = accS; warpCnt[wid] = accC; }
    __syncthreads();

    if (wid == 0) {
        float s = (lane < THREADS / 32) ? warpSum[lane] : 0.f;
        int   c = (lane < THREADS / 32) ? warpCnt[lane] : 0;
        #pragma unroll
        for (int o = 4; o > 0; o >>= 1) {
            s += __shfl_down_sync(0xffffffffu, s, o);
            c += __shfl_down_sync(0xffffffffu, c, o);
        }
        if (lane == 0) {
            if (c > 0) {
                atomicAdd(&g_sum[f], s);
                atomicAdd(&g_cnt[f], c);
            }
            __threadfence();
            unsigned t = atomicAdd(&g_done, 1u);
            if (t == (unsigned)(GRID - 1)) {
                float total = 0.f;
                int   nf = 0;
                #pragma unroll 8
                for (int ff = 0; ff < F_FRAMES; ff++) {
                    float ss = *((volatile float*)&g_sum[ff]);
                    int   cc = *((volatile int*)&g_cnt[ff]);
                    if (cc > 0) { total += ss / (float)cc; nf++; }
                    g_sum[ff] = 0.f;
                    g_cnt[ff] = 0;
                }
                float avg = (nf > 0) ? (total / (float)nf) : 0.f;
                float oqx = quat[0], oqy = quat[1], oqz = quat[2], oqw = quat[3];
                float tx = trans[0], ty = trans[1], tz = trans[2];
                float nrm = sqrtf(oqx*oqx + oqy*oqy + oqz*oqz + oqw*oqw);
                float dq  = 1.f - nrm;
                float reg = 0.01f * (tx*tx + ty*ty + tz*tz + dq*dq);
                out[0] = avg + reg;
                __threadfence();
                g_done = 0u;
            }
        }
    }
}

extern "C" void kernel_launch(void* const* d_in, const int* in_sizes, int n_in,
                              void* d_out, int out_size)
{
    const float* points = (const float*)d_in[0];
    const float* bboxes = (const float*)d_in[1];
    const int*   inL    = (const int*)  d_in[2];
    const int*   inR    = (const int*)  d_in[3];
    const float* quat   = (const float*)d_in[4];
    const float* trans  = (const float*)d_in[5];
    const float* K      = (const float*)d_in[6];
    float*       out    = (float*)d_out;
    (void)in_sizes; (void)n_in; (void)out_size;

    calib_loss_kernel<<<GRID, THREADS>>>(points, bboxes, inL, inR, quat, trans, K, out);
}

// round 10
// speedup vs baseline: 2.8283x; 2.6630x over previous
#include <cuda_runtime.h>
#include <cstdint>

#define F_FRAMES 64
#define N_PTS    4096
#define M_BOX    128
#define BLOCKS_PER_FRAME 16
#define PTS_PER_BLOCK    (N_PTS / BLOCKS_PER_FRAME)   // 256
#define THREADS  256
#define GRID     (F_FRAMES * BLOCKS_PER_FRAME)        // 1024

// pair-interleaved tables: float4 = (ncx0, ncx1, ncy0, ncy1); 66 pairs = 132 center slots
#define TAB_PAIRS 66

__device__ float    g_sum[F_FRAMES];
__device__ int      g_cnt[F_FRAMES];

__device__ __forceinline__ uint64_t pack2(float lo, float hi) {
    uint64_t r; asm("mov.b64 %0, {%1, %2};" : "=l"(r) : "f"(lo), "f"(hi)); return r;
}
__device__ __forceinline__ void unpack2(float& lo, float& hi, uint64_t v) {
    asm("mov.b64 {%0, %1}, %2;" : "=f"(lo), "=f"(hi) : "l"(v));
}
__device__ __forceinline__ uint64_t add2(uint64_t a, uint64_t b) {
    uint64_t r; asm("add.rn.f32x2 %0, %1, %2;" : "=l"(r) : "l"(a), "l"(b)); return r;
}
__device__ __forceinline__ uint64_t mul2(uint64_t a, uint64_t b) {
    uint64_t r; asm("mul.rn.f32x2 %0, %1, %2;" : "=l"(r) : "l"(a), "l"(b)); return r;
}
__device__ __forceinline__ uint64_t fma2(uint64_t a, uint64_t b, uint64_t c) {
    uint64_t r; asm("fma.rn.f32x2 %0, %1, %2, %3;" : "=l"(r) : "l"(a), "l"(b), "l"(c)); return r;
}

__global__ __launch_bounds__(THREADS)
void calib_loss_kernel(const float* __restrict__ points,
                       const float* __restrict__ bboxes,
                       const int*   __restrict__ inL,
                       const int*   __restrict__ inR,
                       const float* __restrict__ quat,
                       const float* __restrict__ trans,
                       const float* __restrict__ K)
{
    __shared__ float4 sTL[TAB_PAIRS];
    __shared__ float4 sTR[TAB_PAIRS];
    __shared__ int    nCL, nCR;
    __shared__ float  warpSum[THREADS / 32];
    __shared__ int    warpCnt[THREADS / 32];

    const int tid  = threadIdx.x;
    const int lane = tid & 31;
    const int wid  = tid >> 5;
    const int f    = blockIdx.x / BLOCKS_PER_FRAME;
    const int blk  = blockIdx.x % BLOCKS_PER_FRAME;

    if (tid == 0) { nCL = 0; nCR = 0; }
    // sentinel prefill (negated-center convention: -(-1e18) never wins a min)
    if (tid < 2 * TAB_PAIRS) {
        float4 s = make_float4(-1e18f, -1e18f, -1e18f, -1e18f);
        if (tid < TAB_PAIRS) sTL[tid] = s; else sTR[tid - TAB_PAIRS] = s;
    }
    __syncthreads();

    // ---- Compact valid centers (negated) into pair-interleaved tables ----
    if (tid < M_BOX) {
        int j = tid;
        const float* bb = bboxes + ((size_t)f * M_BOX + j) * 4;
        float ncx = -bb[0], ncy = -bb[1];
        bool fl = inL[f * M_BOX + j] > 0;
        bool fr = inR[f * M_BOX + j] > 0;
        unsigned ml = __ballot_sync(0xffffffffu, fl);
        if (ml) {
            int leader = __ffs(ml) - 1;
            int base = 0;
            if (lane == leader) base = atomicAdd(&nCL, __popc(ml));
            base = __shfl_sync(0xffffffffu, base, leader);
            if (fl) {
                int i = base + __popc(ml & ((1u << lane) - 1u));
                float* e = (float*)&sTL[i >> 1];
                e[i & 1] = ncx; e[2 + (i & 1)] = ncy;
            }
        }
        unsigned mr = __ballot_sync(0xffffffffu, fr);
        if (mr) {
            int leader = __ffs(mr) - 1;
            int base = 0;
            if (lane == leader) base = atomicAdd(&nCR, __popc(mr));
            base = __shfl_sync(0xffffffffu, base, leader);
            if (fr) {
                int i = base + __popc(mr & ((1u << lane) - 1u));
                float* e = (float*)&sTR[i >> 1];
                e[i & 1] = ncx; e[2 + (i & 1)] = ncy;
            }
        }
    }

    // ---- Fold projection: A = K@R (normalized quaternion), b = K@t ----
    const float oqx = quat[0], oqy = quat[1], oqz = quat[2], oqw = quat[3];
    float qn = rsqrtf(oqx*oqx + oqy*oqy + oqz*oqz + oqw*oqw);
    float qx = oqx*qn, qy = oqy*qn, qz = oqz*qn, qw = oqw*qn;
    float R00 = 1.f - 2.f*(qy*qy + qz*qz), R01 = 2.f*(qx*qy - qz*qw), R02 = 2.f*(qx*qz + qy*qw);
    float R10 = 2.f*(qx*qy + qz*qw), R11 = 1.f - 2.f*(qx*qx + qz*qz), R12 = 2.f*(qy*qz - qx*qw);
    float R20 = 2.f*(qx*qz - qy*qw), R21 = 2.f*(qy*qz + qx*qw), R22 = 1.f - 2.f*(qx*qx + qy*qy);
    const float tx = trans[0], ty = trans[1], tz = trans[2];
    const float k00 = K[0], k01 = K[1], k02 = K[2];
    const float k10 = K[3], k11 = K[4], k12 = K[5];
    const float k20 = K[6], k21 = K[7], k22 = K[8];
    float a00 = k00*R00 + k01*R10 + k02*R20, a01 = k00*R01 + k01*R11 + k02*R21, a02 = k00*R02 + k01*R12 + k02*R22;
    float a10 = k10*R00 + k11*R10 + k12*R20, a11 = k10*R01 + k11*R11 + k12*R21, a12 = k10*R02 + k11*R12 + k12*R22;
    float a20 = k20*R00 + k21*R10 + k22*R20, a21 = k20*R01 + k21*R11 + k22*R21, a22 = k20*R02 + k21*R12 + k22*R22;
    float b0 = k00*tx + k01*ty + k02*tz;
    float b1 = k10*tx + k11*ty + k12*tz;
    float b2 = k20*tx + k21*ty + k22*tz;

    __syncthreads();

    const int cntL = nCL, cntR = nCR;
    // ONE blockwide loop bound for both tables: multiple of 4 centers (2 pairs)
    const int maxC   = (cntL > cntR) ? cntL : cntR;
    const int nPairs = ((maxC + 3) & ~3) >> 1;

    // ---- One point per thread: packed-f32x2 scan, uniform trip count ----
    float accS = 0.f;
    int   accC = 0;
    {
        int n = blk * PTS_PER_BLOCK + tid;
        const float* pt = points + ((size_t)f * N_PTS + n) * 5;
        float x  = pt[0], y = pt[1], z = pt[2], vy = pt[4];

        const ulonglong2* cp = (vy > 0.f) ? (const ulonglong2*)sTL
                                          : (const ulonglong2*)sTR;
        const bool pv = ((vy > 0.f) && (cntL > 0)) || ((vy < 0.f) && (cntR > 0));

        float w  = fmaf(a20, x, fmaf(a21, y, fmaf(a22, z, b2)));
        float iw = __fdividef(1.f, w);
        float u  = fmaf(a00, x, fmaf(a01, y, fmaf(a02, z, b0))) * iw;
        float v  = fmaf(a10, x, fmaf(a11, y, fmaf(a12, z, b1))) * iw;
        uint64_t UU = pack2(u, u);
        uint64_t VV = pack2(v, v);

        float m0 = 3.9e37f, m1 = 3.9e37f, m2 = 3.9e37f, m3 = 3.9e37f;
        #pragma unroll 2
        for (int k = 0; k < nPairs; k += 2) {
            ulonglong2 t0 = cp[k];
            ulonglong2 t1 = cp[k + 1];
            uint64_t dx0 = add2(UU, t0.x);       // u - cx (centers stored negated)
            uint64_t dy0 = add2(VV, t0.y);
            uint64_t dx1 = add2(UU, t1.x);
            uint64_t dy1 = add2(VV, t1.y);
            uint64_t dd0 = fma2(dx0, dx0, mul2(dy0, dy0));
            uint64_t dd1 = fma2(dx1, dx1, mul2(dy1, dy1));
            float a, b, c, d;
            unpack2(a, b, dd0);
            unpack2(c, d, dd1);
            m0 = fminf(m0, a); m1 = fminf(m1, b);
            m2 = fminf(m2, c); m3 = fminf(m3, d);
        }
        float dmin2 = fminf(fminf(m0, m1), fminf(m2, m3));
        float ds = sqrtf(dmin2);
        float h  = (ds <= 50.f) ? (0.5f * dmin2) : (50.f * (ds - 25.f));
        accS = pv ? h : 0.f;
        accC = pv ? 1 : 0;
    }

    // ---- Block reduction ----
    #pragma unroll
    for (int o = 16; o > 0; o >>= 1) {
        accS += __shfl_down_sync(0xffffffffu, accS, o);
        accC += __shfl_down_sync(0xffffffffu, accC, o);
    }
    if (lane == 0) { warpSum[wid] = accS; warpCnt[wid] = accC; }
    __syncthreads();

    if (wid == 0) {
        float s = (lane < THREADS / 32) ? warpSum[lane] : 0.f;
        int   c = (lane < THREADS / 32) ? warpCnt[lane] : 0;
        #pragma unroll
        for (int o = 4; o > 0; o >>= 1) {
            s += __shfl_down_sync(0xffffffffu, s, o);
            c += __shfl_down_sync(0xffffffffu, c, o);
        }
        if (lane == 0 && c > 0) {
            atomicAdd(&g_sum[f], s);
            atomicAdd(&g_cnt[f], c);
        }
    }
}

// Tiny finish kernel: one frame per thread, parallel loads, then reduce.
// Also resets g_sum/g_cnt so every graph replay starts from zero.
__global__ __launch_bounds__(F_FRAMES)
void finish_kernel(const float* __restrict__ quat,
                   const float* __restrict__ trans,
                   float*       __restrict__ out)
{
    __shared__ float sS[2];
    __shared__ int   sC[2];
    const int t    = threadIdx.x;          // 0..63
    const int lane = t & 31;
    const int wid  = t >> 5;

    float ss = g_sum[t];
    int   cc = g_cnt[t];
    g_sum[t] = 0.f;
    g_cnt[t] = 0;

    float fl = (cc > 0) ? (ss / (float)cc) : 0.f;
    int   nz = (cc > 0) ? 1 : 0;

    #pragma unroll
    for (int o = 16; o > 0; o >>= 1) {
        fl += __shfl_down_sync(0xffffffffu, fl, o);
        nz += __shfl_down_sync(0xffffffffu, nz, o);
    }
    if (lane == 0) { sS[wid] = fl; sC[wid] = nz; }
    __syncthreads();

    if (t == 0) {
        float total = sS[0] + sS[1];
        int   nf    = sC[0] + sC[1];
        float avg = (nf > 0) ? (total / (float)nf) : 0.f;
        float oqx = quat[0], oqy = quat[1], oqz = quat[2], oqw = quat[3];
        float tx = trans[0], ty = trans[1], tz = trans[2];
        float nrm = sqrtf(oqx*oqx + oqy*oqy + oqz*oqz + oqw*oqw);
        float dq  = 1.f - nrm;
        float reg = 0.01f * (tx*tx + ty*ty + tz*tz + dq*dq);
        out[0] = avg + reg;
    }
}

extern "C" void kernel_launch(void* const* d_in, const int* in_sizes, int n_in,
                              void* d_out, int out_size)
{
    const float* points = (const float*)d_in[0];
    const float* bboxes = (const float*)d_in[1];
    const int*   inL    = (const int*)  d_in[2];
    const int*   inR    = (const int*)  d_in[3];
    const float* quat   = (const float*)d_in[4];
    const float* trans  = (const float*)d_in[5];
    const float* K      = (const float*)d_in[6];
    float*       out    = (float*)d_out;
    (void)in_sizes; (void)n_in; (void)out_size;

    calib_loss_kernel<<<GRID, THREADS>>>(points, bboxes, inL, inR, quat, trans, K);
    finish_kernel<<<1, F_FRAMES>>>(quat, trans, out);
}